// round 15
// baseline (speedup 1.0000x reference)
#include <cuda_runtime.h>

#define T_DIM 512
#define TPB   128
#define N_STEPS 5

__device__ __forceinline__ float sqrt_approx(float x) {
    float r; asm("sqrt.approx.f32 %0, %1;" : "=f"(r) : "f"(x)); return r;
}
__device__ __forceinline__ float rcp_approx(float x) {
    float r; asm("rcp.approx.f32 %0, %1;" : "=f"(r) : "f"(x)); return r;
}

// sign(x)*(sqrt(|x|+1)-1) + EPS*x — approx sqrt safe (absolute accuracy only).
__device__ __forceinline__ float rescale_f(float x) {
    const float EPS = 1e-3f;
    float t = fabsf(x) + 1.0f;
    return fmaf(EPS, x, copysignf(sqrt_approx(t) - 1.0f, x));
}

// Cancellation-stable: (sqrt(s)-1)/(2e) = 2(|x|+1+e)/(1+sqrt(s)).
__device__ __forceinline__ float inv_rescale_f(float x) {
    const float EPS = 1e-3f;
    float a = fabsf(x) + (1.0f + EPS);
    float s = fmaf(4.0f * EPS, a, 1.0f);
    float r = (2.0f * a) * rcp_approx(1.0f + sqrt_approx(s));
    return copysignf(fmaf(r, r, -1.0f), x);
}

__global__ __launch_bounds__(TPB, 6)
void nstep_qloss_kernel(const float* __restrict__ cq,
                        const float* __restrict__ nq,
                        const float* __restrict__ logp,
                        const float* __restrict__ rw,
                        const float* __restrict__ done,
                        const float* __restrict__ mask,
                        float* __restrict__ out)
{
    // A[t] = m*reward + gamma*inv_qw*(md*logp/3); zero-padded 4 past row end
    __shared__ float4 s_A[T_DIM + 4];

    const float GAMMA  = 0.997f;
    const float GAMMA2 = 0.997f * 0.997f;
    const float GAMMA3 = GAMMA2 * 0.997f;
    const float GAMMA4 = GAMMA3 * 0.997f;
    const float GAMMA5 = GAMMA4 * 0.997f;
    const float LN_GAMMA = -0.003004509021390342f; // ln(0.997)

    const int b   = blockIdx.x;
    const int l   = threadIdx.x;
    const int t0  = 4 * l;
    const int row = b * T_DIM;
    const int bt0 = row + t0;               // float4-unit index (Q=4 streams)
    const int sc4 = b * TPB + l;             // float4-unit index (scalar streams)
    const bool last = (l == TPB - 1);        // t0 = 508; all gathers clamp to 511

    // ---- phase 1: staging-critical loads ----
    float4 m4 = ((const float4*)mask)[sc4];
    float4 d4 = ((const float4*)done)[sc4];
    float4 p4 = ((const float4*)logp)[sc4];
    float4 r0 = ((const float4*)rw)[bt0];
    float4 r1 = ((const float4*)rw)[bt0 + 1];
    float4 r2 = ((const float4*)rw)[bt0 + 2];
    float4 r3 = ((const float4*)rw)[bt0 + 3];
    // gathered mask/done window (t0+4..t0+7) = neighbor thread's float4
    const int gsc = last ? sc4 : sc4 + 1;
    float4 mg = ((const float4*)mask)[gsc];
    float4 dg = ((const float4*)done)[gsc];
    // gathered nq window, clamped at 511 for the last thread
    const int nbase = last ? bt0 + 3 : bt0 + 4;
    const int nstep = last ? 0 : 1;
    float4 n0 = ((const float4*)nq)[nbase];
    float4 n1 = ((const float4*)nq)[nbase + nstep];
    float4 n2 = ((const float4*)nq)[nbase + 2 * nstep];
    float4 n3 = ((const float4*)nq)[nbase + 3 * nstep];

    // per-element A values (x,y,w; z dead). inv_qw = [1,2,-,0.5]
    const float lb0 = (GAMMA / 3.0f) * (m4.x * (1.0f - d4.x)) * p4.x;
    const float lb1 = (GAMMA / 3.0f) * (m4.y * (1.0f - d4.y)) * p4.y;
    const float lb2 = (GAMMA / 3.0f) * (m4.z * (1.0f - d4.z)) * p4.z;
    const float lb3 = (GAMMA / 3.0f) * (m4.w * (1.0f - d4.w)) * p4.w;

    float a0x = fmaf(m4.x, r0.x, lb0), a0y = fmaf(m4.x, r0.y, 2.0f * lb0), a0w = fmaf(m4.x, r0.w, 0.5f * lb0);
    float a1x = fmaf(m4.y, r1.x, lb1), a1y = fmaf(m4.y, r1.y, 2.0f * lb1), a1w = fmaf(m4.y, r1.w, 0.5f * lb1);
    float a2x = fmaf(m4.z, r2.x, lb2), a2y = fmaf(m4.z, r2.y, 2.0f * lb2), a2w = fmaf(m4.z, r2.w, 0.5f * lb2);
    float a3x = fmaf(m4.w, r3.x, lb3), a3y = fmaf(m4.w, r3.y, 2.0f * lb3), a3w = fmaf(m4.w, r3.w, 0.5f * lb3);

    s_A[t0]     = make_float4(a0x, a0y, 0.f, a0w);
    s_A[t0 + 1] = make_float4(a1x, a1y, 0.f, a1w);
    s_A[t0 + 2] = make_float4(a2x, a2y, 0.f, a2w);
    s_A[t0 + 3] = make_float4(a3x, a3y, 0.f, a3w);
    if (l < 4)
        s_A[T_DIM + l] = make_float4(0.f, 0.f, 0.f, 0.f);

    // ---- phase 2: epilogue loads issued while staging drains ----
    float4 c0 = ((const float4*)cq)[bt0];
    float4 c1 = ((const float4*)cq)[bt0 + 1];
    float4 c2 = ((const float4*)cq)[bt0 + 2];
    float4 c3 = ((const float4*)cq)[bt0 + 3];

    // gathered mask/done with last-lane clamp (select, no divergence)
    const float mi0 = last ? m4.w : mg.x, mi1 = last ? m4.w : mg.y;
    const float mi2 = last ? m4.w : mg.z, mi3 = last ? m4.w : mg.w;
    const float di0 = last ? d4.w : dg.x, di1 = last ? d4.w : dg.y;
    const float di2 = last ? d4.w : dg.z, di3 = last ? d4.w : dg.w;

    const float mdi0 = mi0 * (1.0f - di0);
    const float mdi1 = mi1 * (1.0f - di1);
    const float mdi2 = mi2 * (1.0f - di2);
    const float mdi3 = mi3 * (1.0f - di3);
    float v0x = mdi0 * inv_rescale_f(n0.x), v0y = mdi0 * inv_rescale_f(n0.y), v0w = mdi0 * inv_rescale_f(n0.w);
    float v1x = mdi1 * inv_rescale_f(n1.x), v1y = mdi1 * inv_rescale_f(n1.y), v1w = mdi1 * inv_rescale_f(n1.w);
    float v2x = mdi2 * inv_rescale_f(n2.x), v2y = mdi2 * inv_rescale_f(n2.y), v2w = mdi2 * inv_rescale_f(n2.w);
    float v3x = mdi3 * inv_rescale_f(n3.x), v3y = mdi3 * inv_rescale_f(n3.y), v3w = mdi3 * inv_rescale_f(n3.w);

    __syncthreads();

    // window tail A[t0+4 .. t0+7] from shared (4 LDS.128 serve 4 outputs)
    float4 B4 = s_A[t0 + 4];
    float4 B5 = s_A[t0 + 5];
    float4 B6 = s_A[t0 + 6];
    float4 B7 = s_A[t0 + 7];

    // rs(t) = sum_{n=0..4} gamma^n A[t+n]; recurrence rs(t)=A[t]+g*rs(t+1)-g^5*A[t+5]
    float rs3x = fmaf(GAMMA4, B7.x, fmaf(GAMMA3, B6.x, fmaf(GAMMA2, B5.x, fmaf(GAMMA, B4.x, a3x))));
    float rs3y = fmaf(GAMMA4, B7.y, fmaf(GAMMA3, B6.y, fmaf(GAMMA2, B5.y, fmaf(GAMMA, B4.y, a3y))));
    float rs3w = fmaf(GAMMA4, B7.w, fmaf(GAMMA3, B6.w, fmaf(GAMMA2, B5.w, fmaf(GAMMA, B4.w, a3w))));
    float rs2x = fmaf(GAMMA, rs3x, fmaf(-GAMMA5, B7.x, a2x));
    float rs2y = fmaf(GAMMA, rs3y, fmaf(-GAMMA5, B7.y, a2y));
    float rs2w = fmaf(GAMMA, rs3w, fmaf(-GAMMA5, B7.w, a2w));
    float rs1x = fmaf(GAMMA, rs2x, fmaf(-GAMMA5, B6.x, a1x));
    float rs1y = fmaf(GAMMA, rs2y, fmaf(-GAMMA5, B6.y, a1y));
    float rs1w = fmaf(GAMMA, rs2w, fmaf(-GAMMA5, B6.w, a1w));
    float rs0x = fmaf(GAMMA, rs1x, fmaf(-GAMMA5, B5.x, a0x));
    float rs0y = fmaf(GAMMA, rs1y, fmaf(-GAMMA5, B5.y, a0y));
    float rs0w = fmaf(GAMMA, rs1w, fmaf(-GAMMA5, B5.w, a0w));

    // gamma^idx, idx = min(511, t0+4+k); last thread: all idx = 511
    const int   idx0 = last ? (T_DIM - 1) : (t0 + 4);
    const float gi0  = __expf((float)idx0 * LN_GAMMA);
    const float gst  = last ? 1.0f : GAMMA;
    const float gi1  = gi0 * gst;
    const float gi2  = gi1 * gst;
    const float gi3  = gi2 * gst;

    // Q_WEIGHTS = [1, 0.5, 0, 2]
    float e0x = c0.x - rescale_f(fmaf(gi0, v0x, rs0x));
    float e0y = c0.y - rescale_f(fmaf(gi0, v0y, rs0y));
    float e0w = c0.w - rescale_f(fmaf(gi0, v0w, rs0w));
    float e1x = c1.x - rescale_f(fmaf(gi1, v1x, rs1x));
    float e1y = c1.y - rescale_f(fmaf(gi1, v1y, rs1y));
    float e1w = c1.w - rescale_f(fmaf(gi1, v1w, rs1w));
    float e2x = c2.x - rescale_f(fmaf(gi2, v2x, rs2x));
    float e2y = c2.y - rescale_f(fmaf(gi2, v2y, rs2y));
    float e2w = c2.w - rescale_f(fmaf(gi2, v2w, rs2w));
    float e3x = c3.x - rescale_f(fmaf(gi3, v3x, rs3x));
    float e3y = c3.y - rescale_f(fmaf(gi3, v3y, rs3y));
    float e3w = c3.w - rescale_f(fmaf(gi3, v3w, rs3w));

    float4 o0, o1, o2, o3;
    o0.x = 0.5f  * m4.x * e0x * e0x;  o0.y = 0.25f * m4.x * e0y * e0y;  o0.z = 0.0f;  o0.w = m4.x * e0w * e0w;
    o1.x = 0.5f  * m4.y * e1x * e1x;  o1.y = 0.25f * m4.y * e1y * e1y;  o1.z = 0.0f;  o1.w = m4.y * e1w * e1w;
    o2.x = 0.5f  * m4.z * e2x * e2x;  o2.y = 0.25f * m4.z * e2y * e2y;  o2.z = 0.0f;  o2.w = m4.z * e2w * e2w;
    o3.x = 0.5f  * m4.w * e3x * e3x;  o3.y = 0.25f * m4.w * e3y * e3y;  o3.z = 0.0f;  o3.w = m4.w * e3w * e3w;

    ((float4*)out)[bt0]     = o0;
    ((float4*)out)[bt0 + 1] = o1;
    ((float4*)out)[bt0 + 2] = o2;
    ((float4*)out)[bt0 + 3] = o3;
}

extern "C" void kernel_launch(void* const* d_in, const int* in_sizes, int n_in,
                              void* d_out, int out_size)
{
    // metadata order: current_q_value, next_q_value, log_p, reward, is_done, mask
    const float* cq   = (const float*)d_in[0];
    const float* nq   = (const float*)d_in[1];
    const float* logp = (const float*)d_in[2];
    const float* rw   = (const float*)d_in[3];
    const float* done = (const float*)d_in[4];
    const float* mask = (const float*)d_in[5];
    float* out = (float*)d_out;

    int B = in_sizes[2] / T_DIM;   // log_p has B*T elements
    nstep_qloss_kernel<<<B, TPB>>>(cq, nq, logp, rw, done, mask, out);
}

// round 16
// speedup vs baseline: 1.3019x; 1.3019x over previous
#include <cuda_runtime.h>

#define T_DIM 512
#define TPB   256
#define N_STEPS 5

__device__ __forceinline__ float sqrt_approx(float x) {
    float r; asm("sqrt.approx.f32 %0, %1;" : "=f"(r) : "f"(x)); return r;
}
__device__ __forceinline__ float rcp_approx(float x) {
    float r; asm("rcp.approx.f32 %0, %1;" : "=f"(r) : "f"(x)); return r;
}

// sign(x)*(sqrt(|x|+1)-1) + EPS*x — approx sqrt safe (absolute accuracy only).
__device__ __forceinline__ float rescale_f(float x) {
    const float EPS = 1e-3f;
    float t = fabsf(x) + 1.0f;
    return fmaf(EPS, x, copysignf(sqrt_approx(t) - 1.0f, x));
}

// Cancellation-stable: (sqrt(s)-1)/(2e) = 2(|x|+1+e)/(1+sqrt(s)).
__device__ __forceinline__ float inv_rescale_f(float x) {
    const float EPS = 1e-3f;
    float a = fabsf(x) + (1.0f + EPS);
    float s = fmaf(4.0f * EPS, a, 1.0f);
    float r = (2.0f * a) * rcp_approx(1.0f + sqrt_approx(s));
    return copysignf(fmaf(r, r, -1.0f), x);
}

__global__ __launch_bounds__(TPB, 5)
void nstep_qloss_kernel(const float* __restrict__ cq,
                        const float* __restrict__ nq,
                        const float* __restrict__ logp,
                        const float* __restrict__ rw,
                        const float* __restrict__ done,
                        const float* __restrict__ mask,
                        float* __restrict__ out)
{
    // Only A is staged in shared: A[t] = m*reward + gamma*inv_qw*(md*logp/3)
    __shared__ float4 s_A[T_DIM + N_STEPS - 1];

    const float GAMMA  = 0.997f;
    const float GAMMA2 = 0.997f * 0.997f;
    const float GAMMA3 = GAMMA2 * 0.997f;
    const float GAMMA4 = GAMMA3 * 0.997f;
    const float GAMMA5 = GAMMA4 * 0.997f;
    const float LN_GAMMA = -0.003004509021390342f; // ln(0.997)

    const int b   = blockIdx.x;
    const int l   = threadIdx.x;
    const int t0  = 2 * l;
    const int row = b * T_DIM;
    const int bt0 = row + t0;              // float4-unit index for Q=4 streams
    const int sc  = b * TPB + l;           // float2-unit index for scalar streams

    // gathered indices (clamped at row end)
    const int idx0 = min(T_DIM - 1, t0 + 4);
    const int idx1 = min(T_DIM - 1, t0 + 5);

    // ---- front load batch: everything feeding A staging + v (NOT cq) ----
    float2 m2 = ((const float2*)mask)[sc];
    float2 d2 = ((const float2*)done)[sc];
    float2 p2 = ((const float2*)logp)[sc];
    float4 r0 = ((const float4*)rw)[bt0];
    float4 r1 = ((const float4*)rw)[bt0 + 1];
    // gathered scalars: clamped pair load + select (no divergent branch)
    const int gp = min(sc + 2, b * TPB + TPB - 1);
    float2 mg = ((const float2*)mask)[gp];
    float2 dg = ((const float2*)done)[gp];
    const bool in_rng = (l <= TPB - 3);     // t0+5 <= 511
    float mi0 = in_rng ? mg.x : mg.y;
    float mi1 = mg.y;
    float di0 = in_rng ? dg.x : dg.y;
    float di1 = dg.y;
    float4 n0 = ((const float4*)nq)[row + idx0];
    float4 n1 = ((const float4*)nq)[row + idx1];

    const float md0 = m2.x * (1.0f - d2.x);
    const float md1 = m2.y * (1.0f - d2.y);
    const float lb0 = (GAMMA / 3.0f) * md0 * p2.x;   // per-lane *inv_qw = [1,2,-,0.5]
    const float lb1 = (GAMMA / 3.0f) * md1 * p2.y;

    float4 a0, a1;
    a0.x = fmaf(m2.x, r0.x, lb0);
    a0.y = fmaf(m2.x, r0.y, 2.0f * lb0);
    a0.z = 0.0f;
    a0.w = fmaf(m2.x, r0.w, 0.5f * lb0);
    a1.x = fmaf(m2.y, r1.x, lb1);
    a1.y = fmaf(m2.y, r1.y, 2.0f * lb1);
    a1.z = 0.0f;
    a1.w = fmaf(m2.y, r1.w, 0.5f * lb1);
    s_A[t0]     = a0;
    s_A[t0 + 1] = a1;
    if (l < 2) {
        s_A[T_DIM + 2 * l]     = make_float4(0.f, 0.f, 0.f, 0.f);
        s_A[T_DIM + 2 * l + 1] = make_float4(0.f, 0.f, 0.f, 0.f);
    }

    // epilogue-only loads, streaming (read-once; don't pollute L2 for the
    // reused gather lines). Issued after staging stores.
    float4 c0 = __ldcs(((const float4*)cq) + bt0);
    float4 c1 = __ldcs(((const float4*)cq) + bt0 + 1);

    // gathered next-q term computed directly in registers (overlaps barrier)
    const float mdi0 = mi0 * (1.0f - di0);
    const float mdi1 = mi1 * (1.0f - di1);
    float v0x = mdi0 * inv_rescale_f(n0.x);
    float v0y = mdi0 * inv_rescale_f(n0.y);
    float v0w = mdi0 * inv_rescale_f(n0.w);
    float v1x = mdi1 * inv_rescale_f(n1.x);
    float v1y = mdi1 * inv_rescale_f(n1.y);
    float v1w = mdi1 * inv_rescale_f(n1.w);

    __syncthreads();

    // window values A[t0+2 .. t0+5] from shared; A[t0], A[t0+1] in regs
    float4 A2 = s_A[t0 + 2];
    float4 A3 = s_A[t0 + 3];
    float4 A4 = s_A[t0 + 4];
    float4 A5 = s_A[t0 + 5];

    // rs1 = sum_{n=0..4} gamma^n A[t0+1+n]
    float rs1x = fmaf(GAMMA4, A5.x, fmaf(GAMMA3, A4.x, fmaf(GAMMA2, A3.x, fmaf(GAMMA, A2.x, a1.x))));
    float rs1y = fmaf(GAMMA4, A5.y, fmaf(GAMMA3, A4.y, fmaf(GAMMA2, A3.y, fmaf(GAMMA, A2.y, a1.y))));
    float rs1w = fmaf(GAMMA4, A5.w, fmaf(GAMMA3, A4.w, fmaf(GAMMA2, A3.w, fmaf(GAMMA, A2.w, a1.w))));
    // rs0 = A[t0] + gamma*rs1 - gamma^5 * A[t0+5]
    float rs0x = fmaf(GAMMA, rs1x, fmaf(-GAMMA5, A5.x, a0.x));
    float rs0y = fmaf(GAMMA, rs1y, fmaf(-GAMMA5, A5.y, a0.y));
    float rs0w = fmaf(GAMMA, rs1w, fmaf(-GAMMA5, A5.w, a0.w));

    const float gi0 = __expf((float)idx0 * LN_GAMMA);        // gamma^idx (absolute)
    const float gi1 = (idx1 == idx0) ? gi0 : gi0 * GAMMA;

    // Q_WEIGHTS = [1, 0.5, 0, 2]
    float e0x = c0.x - rescale_f(fmaf(gi0, v0x, rs0x));
    float e0y = c0.y - rescale_f(fmaf(gi0, v0y, rs0y));
    float e0w = c0.w - rescale_f(fmaf(gi0, v0w, rs0w));
    float e1x = c1.x - rescale_f(fmaf(gi1, v1x, rs1x));
    float e1y = c1.y - rescale_f(fmaf(gi1, v1y, rs1y));
    float e1w = c1.w - rescale_f(fmaf(gi1, v1w, rs1w));

    float4 o0, o1;
    o0.x = 0.5f  * m2.x * e0x * e0x;
    o0.y = 0.25f * m2.x * e0y * e0y;
    o0.z = 0.0f;
    o0.w = m2.x * e0w * e0w;
    o1.x = 0.5f  * m2.y * e1x * e1x;
    o1.y = 0.25f * m2.y * e1y * e1y;
    o1.z = 0.0f;
    o1.w = m2.y * e1w * e1w;

    // streaming stores: write-once, never re-read — evict-first policy
    __stcs(((float4*)out) + bt0,     o0);
    __stcs(((float4*)out) + bt0 + 1, o1);
}

extern "C" void kernel_launch(void* const* d_in, const int* in_sizes, int n_in,
                              void* d_out, int out_size)
{
    // metadata order: current_q_value, next_q_value, log_p, reward, is_done, mask
    const float* cq   = (const float*)d_in[0];
    const float* nq   = (const float*)d_in[1];
    const float* logp = (const float*)d_in[2];
    const float* rw   = (const float*)d_in[3];
    const float* done = (const float*)d_in[4];
    const float* mask = (const float*)d_in[5];
    float* out = (float*)d_out;

    int B = in_sizes[2] / T_DIM;   // log_p has B*T elements
    nstep_qloss_kernel<<<B, TPB>>>(cq, nq, logp, rw, done, mask, out);
}

// round 17
// speedup vs baseline: 1.5186x; 1.1664x over previous
#include <cuda_runtime.h>

#define T_DIM 512
#define TPB   256
#define N_STEPS 5

__device__ __forceinline__ float sqrt_approx(float x) {
    float r; asm("sqrt.approx.f32 %0, %1;" : "=f"(r) : "f"(x)); return r;
}
__device__ __forceinline__ float rcp_approx(float x) {
    float r; asm("rcp.approx.f32 %0, %1;" : "=f"(r) : "f"(x)); return r;
}

// sign(x)*(sqrt(|x|+1)-1) + EPS*x — approx sqrt safe (absolute accuracy only).
__device__ __forceinline__ float rescale_f(float x) {
    const float EPS = 1e-3f;
    float t = fabsf(x) + 1.0f;
    return fmaf(EPS, x, copysignf(sqrt_approx(t) - 1.0f, x));
}

// Cancellation-stable: (sqrt(s)-1)/(2e) = 2(|x|+1+e)/(1+sqrt(s)).
__device__ __forceinline__ float inv_rescale_f(float x) {
    const float EPS = 1e-3f;
    float a = fabsf(x) + (1.0f + EPS);
    float s = fmaf(4.0f * EPS, a, 1.0f);
    float r = (2.0f * a) * rcp_approx(1.0f + sqrt_approx(s));
    return copysignf(fmaf(r, r, -1.0f), x);
}

__global__ __launch_bounds__(TPB, 5)
void nstep_qloss_kernel(const float* __restrict__ cq,
                        const float* __restrict__ nq,
                        const float* __restrict__ logp,
                        const float* __restrict__ rw,
                        const float* __restrict__ done,
                        const float* __restrict__ mask,
                        float* __restrict__ out)
{
    // Only A is staged in shared: A[t] = m*reward + gamma*inv_qw*(md*logp/3)
    __shared__ float4 s_A[T_DIM + N_STEPS - 1];

    const float GAMMA  = 0.997f;
    const float GAMMA2 = 0.997f * 0.997f;
    const float GAMMA3 = GAMMA2 * 0.997f;
    const float GAMMA4 = GAMMA3 * 0.997f;
    const float GAMMA5 = GAMMA4 * 0.997f;
    const float LN_GAMMA = -0.003004509021390342f; // ln(0.997)

    const int b   = blockIdx.x;
    const int l   = threadIdx.x;
    const int t0  = 2 * l;
    const int row = b * T_DIM;
    const int bt0 = row + t0;              // float4-unit index for Q=4 streams
    const int sc  = b * TPB + l;           // float2-unit index for scalar streams

    // gathered indices (clamped at row end)
    const int idx0 = min(T_DIM - 1, t0 + 4);
    const int idx1 = min(T_DIM - 1, t0 + 5);

    // ---- front load batch: everything feeding A staging + v (NOT cq) ----
    // mask/done are read twice (own + gathered by a neighbor thread): cached.
    float2 m2 = ((const float2*)mask)[sc];
    float2 d2 = ((const float2*)done)[sc];
    // logp/rw/nq are read exactly once per address: streaming (evict-first).
    float2 p2 = __ldcs(((const float2*)logp) + sc);
    float4 r0 = __ldcs(((const float4*)rw) + bt0);
    float4 r1 = __ldcs(((const float4*)rw) + bt0 + 1);
    // gathered scalars: clamped pair load + select (no divergent branch)
    const int gp = min(sc + 2, b * TPB + TPB - 1);
    float2 mg = ((const float2*)mask)[gp];
    float2 dg = ((const float2*)done)[gp];
    const bool in_rng = (l <= TPB - 3);     // t0+5 <= 511
    float mi0 = in_rng ? mg.x : mg.y;
    float mi1 = mg.y;
    float di0 = in_rng ? dg.x : dg.y;
    float di1 = dg.y;
    float4 n0 = __ldcs(((const float4*)nq) + row + idx0);
    float4 n1 = __ldcs(((const float4*)nq) + row + idx1);

    const float md0 = m2.x * (1.0f - d2.x);
    const float md1 = m2.y * (1.0f - d2.y);
    const float lb0 = (GAMMA / 3.0f) * md0 * p2.x;   // per-lane *inv_qw = [1,2,-,0.5]
    const float lb1 = (GAMMA / 3.0f) * md1 * p2.y;

    float4 a0, a1;
    a0.x = fmaf(m2.x, r0.x, lb0);
    a0.y = fmaf(m2.x, r0.y, 2.0f * lb0);
    a0.z = 0.0f;
    a0.w = fmaf(m2.x, r0.w, 0.5f * lb0);
    a1.x = fmaf(m2.y, r1.x, lb1);
    a1.y = fmaf(m2.y, r1.y, 2.0f * lb1);
    a1.z = 0.0f;
    a1.w = fmaf(m2.y, r1.w, 0.5f * lb1);
    s_A[t0]     = a0;
    s_A[t0 + 1] = a1;
    if (l < 2) {
        s_A[T_DIM + 2 * l]     = make_float4(0.f, 0.f, 0.f, 0.f);
        s_A[T_DIM + 2 * l + 1] = make_float4(0.f, 0.f, 0.f, 0.f);
    }

    // epilogue-only loads, streaming (read-once). Issued after staging stores.
    float4 c0 = __ldcs(((const float4*)cq) + bt0);
    float4 c1 = __ldcs(((const float4*)cq) + bt0 + 1);

    // gathered next-q term computed directly in registers (overlaps barrier)
    const float mdi0 = mi0 * (1.0f - di0);
    const float mdi1 = mi1 * (1.0f - di1);
    float v0x = mdi0 * inv_rescale_f(n0.x);
    float v0y = mdi0 * inv_rescale_f(n0.y);
    float v0w = mdi0 * inv_rescale_f(n0.w);
    float v1x = mdi1 * inv_rescale_f(n1.x);
    float v1y = mdi1 * inv_rescale_f(n1.y);
    float v1w = mdi1 * inv_rescale_f(n1.w);

    __syncthreads();

    // window values A[t0+2 .. t0+5] from shared; A[t0], A[t0+1] in regs
    float4 A2 = s_A[t0 + 2];
    float4 A3 = s_A[t0 + 3];
    float4 A4 = s_A[t0 + 4];
    float4 A5 = s_A[t0 + 5];

    // rs1 = sum_{n=0..4} gamma^n A[t0+1+n]
    float rs1x = fmaf(GAMMA4, A5.x, fmaf(GAMMA3, A4.x, fmaf(GAMMA2, A3.x, fmaf(GAMMA, A2.x, a1.x))));
    float rs1y = fmaf(GAMMA4, A5.y, fmaf(GAMMA3, A4.y, fmaf(GAMMA2, A3.y, fmaf(GAMMA, A2.y, a1.y))));
    float rs1w = fmaf(GAMMA4, A5.w, fmaf(GAMMA3, A4.w, fmaf(GAMMA2, A3.w, fmaf(GAMMA, A2.w, a1.w))));
    // rs0 = A[t0] + gamma*rs1 - gamma^5 * A[t0+5]
    float rs0x = fmaf(GAMMA, rs1x, fmaf(-GAMMA5, A5.x, a0.x));
    float rs0y = fmaf(GAMMA, rs1y, fmaf(-GAMMA5, A5.y, a0.y));
    float rs0w = fmaf(GAMMA, rs1w, fmaf(-GAMMA5, A5.w, a0.w));

    const float gi0 = __expf((float)idx0 * LN_GAMMA);        // gamma^idx (absolute)
    const float gi1 = (idx1 == idx0) ? gi0 : gi0 * GAMMA;

    // Q_WEIGHTS = [1, 0.5, 0, 2]
    float e0x = c0.x - rescale_f(fmaf(gi0, v0x, rs0x));
    float e0y = c0.y - rescale_f(fmaf(gi0, v0y, rs0y));
    float e0w = c0.w - rescale_f(fmaf(gi0, v0w, rs0w));
    float e1x = c1.x - rescale_f(fmaf(gi1, v1x, rs1x));
    float e1y = c1.y - rescale_f(fmaf(gi1, v1y, rs1y));
    float e1w = c1.w - rescale_f(fmaf(gi1, v1w, rs1w));

    float4 o0, o1;
    o0.x = 0.5f  * m2.x * e0x * e0x;
    o0.y = 0.25f * m2.x * e0y * e0y;
    o0.z = 0.0f;
    o0.w = m2.x * e0w * e0w;
    o1.x = 0.5f  * m2.y * e1x * e1x;
    o1.y = 0.25f * m2.y * e1y * e1y;
    o1.z = 0.0f;
    o1.w = m2.y * e1w * e1w;

    // streaming stores: write-once, never re-read — evict-first policy
    __stcs(((float4*)out) + bt0,     o0);
    __stcs(((float4*)out) + bt0 + 1, o1);
}

extern "C" void kernel_launch(void* const* d_in, const int* in_sizes, int n_in,
                              void* d_out, int out_size)
{
    // metadata order: current_q_value, next_q_value, log_p, reward, is_done, mask
    const float* cq   = (const float*)d_in[0];
    const float* nq   = (const float*)d_in[1];
    const float* logp = (const float*)d_in[2];
    const float* rw   = (const float*)d_in[3];
    const float* done = (const float*)d_in[4];
    const float* mask = (const float*)d_in[5];
    float* out = (float*)d_out;

    int B = in_sizes[2] / T_DIM;   // log_p has B*T elements
    nstep_qloss_kernel<<<B, TPB>>>(cq, nq, logp, rw, done, mask, out);
}